// round 2
// baseline (speedup 1.0000x reference)
#include <cuda_runtime.h>
#include <cstdint>

// HashGrid3D: 16-level Instant-NGP style hash grid encode.
// xyt: (1048576, 3) fp32 in [0,1); tables: (16, 524288, 2) fp32.
// out: (1048576, 32) fp32.
//
// hash(c) = (cx*1 ^ cy*2654435761 ^ cz*805459861) & (T-1), T = 2^19.
//
// R2: process levels in pairs, store each pair as one float4 immediately
// (kills the 32-float live accumulator), force 48-reg bin via
// __launch_bounds__(256, 5) to raise occupancy 32 -> 40 warps/SM and keep
// the l1tex wavefront queue fed.

#define T_SIZE 524288u
#define HMASK  (T_SIZE - 1u)

__device__ __forceinline__ void level_gather(
    const float2* __restrict__ tbl, int N,
    float x, float y, float z,
    float& r0, float& r1)
{
    const float fN = (float)N;
    float sx = x * fN, sy = y * fN, sz = z * fN;
    float fx = floorf(sx), fy = floorf(sy), fz = floorf(sz);
    float tx = sx - fx, ty = sy - fy, tz = sz - fz;

    int ix = (int)fx, iy = (int)fy, iz = (int)fz;
    if (ix >= N) ix -= N;
    if (iy >= N) iy -= N;
    if (iz >= N) iz -= N;
    int ix1 = ix + 1; if (ix1 >= N) ix1 -= N;
    int iy1 = iy + 1; if (iy1 >= N) iy1 -= N;
    int iz1 = iz + 1; if (iz1 >= N) iz1 -= N;

    const uint32_t hx0 = (uint32_t)ix;                    // prime_x = 1
    const uint32_t hx1 = (uint32_t)ix1;
    const uint32_t hy0 = (uint32_t)iy  * 2654435761u;
    const uint32_t hy1 = (uint32_t)iy1 * 2654435761u;
    const uint32_t hz0 = (uint32_t)iz  * 805459861u;
    const uint32_t hz1 = (uint32_t)iz1 * 805459861u;

    // 8 independent gathers (MLP inside the level)
    const float2 g000 = __ldg(tbl + ((hx0 ^ hy0 ^ hz0) & HMASK));
    const float2 g100 = __ldg(tbl + ((hx1 ^ hy0 ^ hz0) & HMASK));
    const float2 g010 = __ldg(tbl + ((hx0 ^ hy1 ^ hz0) & HMASK));
    const float2 g110 = __ldg(tbl + ((hx1 ^ hy1 ^ hz0) & HMASK));
    const float2 g001 = __ldg(tbl + ((hx0 ^ hy0 ^ hz1) & HMASK));
    const float2 g101 = __ldg(tbl + ((hx1 ^ hy0 ^ hz1) & HMASK));
    const float2 g011 = __ldg(tbl + ((hx0 ^ hy1 ^ hz1) & HMASK));
    const float2 g111 = __ldg(tbl + ((hx1 ^ hy1 ^ hz1) & HMASK));

    const float ux = 1.0f - tx, uy = 1.0f - ty, uz = 1.0f - tz;
    const float wy0z0 = uy * uz, wy1z0 = ty * uz;
    const float wy0z1 = uy * tz, wy1z1 = ty * tz;

    const float w000 = ux * wy0z0, w100 = tx * wy0z0;
    const float w010 = ux * wy1z0, w110 = tx * wy1z0;
    const float w001 = ux * wy0z1, w101 = tx * wy0z1;
    const float w011 = ux * wy1z1, w111 = tx * wy1z1;

    float a = w000 * g000.x;
    float b = w000 * g000.y;
    a = fmaf(w100, g100.x, a);  b = fmaf(w100, g100.y, b);
    a = fmaf(w010, g010.x, a);  b = fmaf(w010, g010.y, b);
    a = fmaf(w110, g110.x, a);  b = fmaf(w110, g110.y, b);
    a = fmaf(w001, g001.x, a);  b = fmaf(w001, g001.y, b);
    a = fmaf(w101, g101.x, a);  b = fmaf(w101, g101.y, b);
    a = fmaf(w011, g011.x, a);  b = fmaf(w011, g011.y, b);
    a = fmaf(w111, g111.x, a);  b = fmaf(w111, g111.y, b);
    r0 = a; r1 = b;
}

__global__ void __launch_bounds__(256, 5) hashgrid3d_kernel(
    const float* __restrict__ xyt,
    const float2* __restrict__ tables,
    float4* __restrict__ out,
    int n)
{
    const int p = blockIdx.x * blockDim.x + threadIdx.x;
    if (p >= n) return;

    const float x = xyt[3 * p + 0];
    const float y = xyt[3 * p + 1];
    const float z = xyt[3 * p + 2];

    // round(16 * 32^(l/15)) for l in 0..15
    const int RES[16] = {16, 20, 25, 32, 40, 51, 64, 81,
                         102, 128, 161, 203, 256, 323, 406, 512};

    float4* o = out + (size_t)p * 8;

#pragma unroll
    for (int g = 0; g < 8; ++g) {
        const int l0 = 2 * g, l1 = 2 * g + 1;
        float4 r;
        level_gather(tables + (size_t)l0 * T_SIZE, RES[l0], x, y, z, r.x, r.y);
        level_gather(tables + (size_t)l1 * T_SIZE, RES[l1], x, y, z, r.z, r.w);
        o[g] = r;
    }
}

extern "C" void kernel_launch(void* const* d_in, const int* in_sizes, int n_in,
                              void* d_out, int out_size)
{
    const float*  xyt    = (const float*)d_in[0];
    const float2* tables = (const float2*)d_in[1];
    float4*       out    = (float4*)d_out;

    const int n = in_sizes[0] / 3;  // 1048576 points
    const int threads = 256;
    const int blocks = (n + threads - 1) / threads;

    hashgrid3d_kernel<<<blocks, threads>>>(xyt, tables, out, n);
}

// round 3
// speedup vs baseline: 1.2193x; 1.2193x over previous
#include <cuda_runtime.h>
#include <cstdint>

// HashGrid3D: 16-level Instant-NGP style hash grid encode.
// xyt: (1048576, 3) fp32 in [0,1); tables: (16, 524288, 2) fp32.
// out: (1048576, 32) fp32.
//
// hash(c) = (cx*1 ^ cy*2654435761 ^ cz*805459861) & (T-1), T = 2^19.
//
// R3: the kernel is L1tex-wavefront bound (R1: L1=88%, more occupancy in R2
// made it worse). Attack the wavefront count itself:
//  (a) x-pair merge: prime_x == 1, so when ix is even h(ix+1) = h(ix)^1 and
//      the two corner entries share one aligned 16B chunk -> LDG.128 replaces
//      two LDG.64 for ~50% of lanes (-25% gather wavefronts).
//  (b) levels 0,1 (N=16,20) served from dense per-CTA smem tables (94.5KB),
//      built once per CTA; persistent-ish grid (148 CTAs x 1024 thr) so the
//      build is 1.4% overhead while removing 12.5% of LDG traffic.

#define T_SIZE 524288u
#define HMASK  (T_SIZE - 1u)
#define PY     2654435761u
#define PZ     805459861u

#define N0 16
#define N1 20
#define S0_ENTRIES (N0 * N0 * N0)          // 4096
#define S1_ENTRIES (N1 * N1 * N1)          // 8000
#define SMEM_BYTES ((S0_ENTRIES + S1_ENTRIES) * 8)  // 96768

struct Corners { float2 g[8]; };

__device__ __forceinline__ void trilerp(
    const Corners& c, float tx, float ty, float tz, float& r0, float& r1)
{
    const float ux = 1.0f - tx, uy = 1.0f - ty, uz = 1.0f - tz;
    const float wy0z0 = uy * uz, wy1z0 = ty * uz;
    const float wy0z1 = uy * tz, wy1z1 = ty * tz;
    const float w000 = ux * wy0z0, w100 = tx * wy0z0;
    const float w010 = ux * wy1z0, w110 = tx * wy1z0;
    const float w001 = ux * wy0z1, w101 = tx * wy0z1;
    const float w011 = ux * wy1z1, w111 = tx * wy1z1;

    float a = w000 * c.g[0].x;
    float b = w000 * c.g[0].y;
    a = fmaf(w100, c.g[1].x, a);  b = fmaf(w100, c.g[1].y, b);
    a = fmaf(w010, c.g[2].x, a);  b = fmaf(w010, c.g[2].y, b);
    a = fmaf(w110, c.g[3].x, a);  b = fmaf(w110, c.g[3].y, b);
    a = fmaf(w001, c.g[4].x, a);  b = fmaf(w001, c.g[4].y, b);
    a = fmaf(w101, c.g[5].x, a);  b = fmaf(w101, c.g[5].y, b);
    a = fmaf(w011, c.g[6].x, a);  b = fmaf(w011, c.g[6].y, b);
    a = fmaf(w111, c.g[7].x, a);  b = fmaf(w111, c.g[7].y, b);
    r0 = a; r1 = b;
}

// fractional coords + wrapped integer corners for resolution N
__device__ __forceinline__ void corner_setup(
    int N, float x, float y, float z,
    int& ix, int& iy, int& iz, int& ix1, int& iy1, int& iz1,
    float& tx, float& ty, float& tz)
{
    const float fN = (float)N;
    float sx = x * fN, sy = y * fN, sz = z * fN;
    float fx = floorf(sx), fy = floorf(sy), fz = floorf(sz);
    tx = sx - fx; ty = sy - fy; tz = sz - fz;
    ix = (int)fx; iy = (int)fy; iz = (int)fz;
    if (ix >= N) ix -= N;
    if (iy >= N) iy -= N;
    if (iz >= N) iz -= N;
    ix1 = ix + 1; if (ix1 >= N) ix1 -= N;
    iy1 = iy + 1; if (iy1 >= N) iy1 -= N;
    iz1 = iz + 1; if (iz1 >= N) iz1 -= N;
}

// hashed LDG level with x-pair LDG.128 merging
__device__ __forceinline__ void level_ldg(
    const float2* __restrict__ tbl, int N,
    float x, float y, float z, float& r0, float& r1)
{
    int ix, iy, iz, ix1, iy1, iz1;
    float tx, ty, tz;
    corner_setup(N, x, y, z, ix, iy, iz, ix1, iy1, iz1, tx, ty, tz);

    const uint32_t hy0 = (uint32_t)iy  * PY, hy1 = (uint32_t)iy1 * PY;
    const uint32_t hz0 = (uint32_t)iz  * PZ, hz1 = (uint32_t)iz1 * PZ;
    const uint32_t ux0 = (uint32_t)ix,  ux1 = (uint32_t)ix1;
    uint32_t s[4];
    s[0] = hy0 ^ hz0; s[1] = hy1 ^ hz0; s[2] = hy0 ^ hz1; s[3] = hy1 ^ hz1;

    Corners c;
    // pairable: ix even (no carry into XOR) and no x-wrap
    const bool pair = ((ix & 1) == 0) && (ix1 == ix + 1);
    if (pair) {
        const float4* __restrict__ tbl4 = (const float4*)tbl;
#pragma unroll
        for (int k = 0; k < 4; ++k) {
            uint32_t h0 = (ux0 ^ s[k]) & HMASK;          // h1 = h0 ^ 1
            float4 q = __ldg(tbl4 + (h0 >> 1));
            if (h0 & 1) { c.g[2*k] = make_float2(q.z, q.w); c.g[2*k+1] = make_float2(q.x, q.y); }
            else        { c.g[2*k] = make_float2(q.x, q.y); c.g[2*k+1] = make_float2(q.z, q.w); }
        }
    } else {
#pragma unroll
        for (int k = 0; k < 4; ++k) {
            uint32_t h0 = (ux0 ^ s[k]) & HMASK;
            uint32_t h1 = (ux1 ^ s[k]) & HMASK;
            c.g[2*k]   = __ldg(tbl + h0);
            c.g[2*k+1] = __ldg(tbl + h1);
        }
    }
    trilerp(c, tx, ty, tz, r0, r1);
}

// dense smem level (no hash)
__device__ __forceinline__ void level_smem(
    const float2* __restrict__ stbl, int N,
    float x, float y, float z, float& r0, float& r1)
{
    int ix, iy, iz, ix1, iy1, iz1;
    float tx, ty, tz;
    corner_setup(N, x, y, z, ix, iy, iz, ix1, iy1, iz1, tx, ty, tz);

    const int y0 = iy * N,  y1 = iy1 * N;
    const int z0 = iz * N * N, z1 = iz1 * N * N;

    Corners c;
    c.g[0] = stbl[z0 + y0 + ix];  c.g[1] = stbl[z0 + y0 + ix1];
    c.g[2] = stbl[z0 + y1 + ix];  c.g[3] = stbl[z0 + y1 + ix1];
    c.g[4] = stbl[z1 + y0 + ix];  c.g[5] = stbl[z1 + y0 + ix1];
    c.g[6] = stbl[z1 + y1 + ix];  c.g[7] = stbl[z1 + y1 + ix1];
    trilerp(c, tx, ty, tz, r0, r1);
}

__global__ void __launch_bounds__(1024, 1) hashgrid3d_kernel(
    const float* __restrict__ xyt,
    const float2* __restrict__ tables,
    float4* __restrict__ out,
    int n)
{
    extern __shared__ float2 smem[];
    float2* s0 = smem;               // level 0: dense 16^3
    float2* s1 = smem + S0_ENTRIES;  // level 1: dense 20^3

    // ---- build dense tables (hash evaluated once per cell per CTA) ----
    {
        const float2* __restrict__ t0 = tables;
        for (int i = threadIdx.x; i < S0_ENTRIES; i += 1024) {
            uint32_t ix =  i        & (N0 - 1);
            uint32_t iy = (i >> 4)  & (N0 - 1);
            uint32_t iz =  i >> 8;
            uint32_t h = (ix ^ (iy * PY) ^ (iz * PZ)) & HMASK;
            s0[i] = __ldg(t0 + h);
        }
        const float2* __restrict__ t1 = tables + T_SIZE;
        for (int i = threadIdx.x; i < S1_ENTRIES; i += 1024) {
            uint32_t ix = i % N1;
            uint32_t r  = i / N1;
            uint32_t iy = r % N1;
            uint32_t iz = r / N1;
            uint32_t h = (ix ^ (iy * PY) ^ (iz * PZ)) & HMASK;
            s1[i] = __ldg(t1 + h);
        }
    }
    __syncthreads();

    // round(16 * 32^(l/15)) for l = 2..15
    const int RES[14] = {25, 32, 40, 51, 64, 81, 102, 128, 161, 203, 256, 323, 406, 512};

    const int stride = gridDim.x * blockDim.x;
    for (int p = blockIdx.x * blockDim.x + threadIdx.x; p < n; p += stride) {
        const float x = xyt[3 * p + 0];
        const float y = xyt[3 * p + 1];
        const float z = xyt[3 * p + 2];

        float4* o = out + (size_t)p * 8;
        float4 r;

        // levels 0,1 from smem
        level_smem(s0, N0, x, y, z, r.x, r.y);
        level_smem(s1, N1, x, y, z, r.z, r.w);
        o[0] = r;

        // levels 2..15 from global, paired LDG.128 when possible
#pragma unroll
        for (int g = 1; g < 8; ++g) {
            const int l0 = 2 * g - 2, l1 = 2 * g - 1;  // indices into RES
            level_ldg(tables + (size_t)(l0 + 2) * T_SIZE, RES[l0], x, y, z, r.x, r.y);
            level_ldg(tables + (size_t)(l1 + 2) * T_SIZE, RES[l1], x, y, z, r.z, r.w);
            o[g] = r;
        }
    }
}

extern "C" void kernel_launch(void* const* d_in, const int* in_sizes, int n_in,
                              void* d_out, int out_size)
{
    const float*  xyt    = (const float*)d_in[0];
    const float2* tables = (const float2*)d_in[1];
    float4*       out    = (float4*)d_out;

    const int n = in_sizes[0] / 3;  // 1048576 points

    static bool attr_set = false;
    if (!attr_set) {
        cudaFuncSetAttribute(hashgrid3d_kernel,
                             cudaFuncAttributeMaxDynamicSharedMemorySize,
                             SMEM_BYTES);
        attr_set = true;
    }

    // persistent-ish: one 1024-thread CTA per SM, grid-stride over points
    hashgrid3d_kernel<<<148, 1024, SMEM_BYTES>>>(xyt, tables, out, n);
}

// round 4
// speedup vs baseline: 1.2309x; 1.0095x over previous
#include <cuda_runtime.h>
#include <cstdint>

// HashGrid3D: 16-level Instant-NGP style hash grid encode.
// xyt: (1048576, 3) fp32 in [0,1); tables: (16, 524288, 2) fp32.
// out: (1048576, 32) fp32.
//
// hash(c) = (cx*1 ^ cy*2654435761 ^ cz*805459861) & (T-1), T = 2^19.
//
// R4: kernel sits exactly on the L1tex wavefront-throughput line (~2700
// wf/warp ~= 330us). Reduce wavefronts structurally:
//  - levels 0,1: dense smem tables (R3, proven)
//  - levels 2-8: DENSE gmem tables built by a pre-kernel, each entry a
//    float4 = (g[x], g[x+1 mod N]) -> exactly 4 LDG.128 per level per lane,
//    no divergence, 1 sector per load (wf 192->128, sectors 6->4 per level)
//  - levels 9-15: hashed with x-parity LDG.128 pairing (R3)

#define T_SIZE 524288u
#define HMASK  (T_SIZE - 1u)
#define PY     2654435761u
#define PZ     805459861u

#define N0 16
#define N1 20
#define S0_ENTRIES (N0 * N0 * N0)          // 4096
#define S1_ENTRIES (N1 * N1 * N1)          // 8000
#define SMEM_BYTES ((S0_ENTRIES + S1_ENTRIES) * 8)  // 96768

// dense levels 2..8: N = 25,32,40,51,64,81,102
#define DENSE_TOTAL 2099837
__device__ float4 g_dense[DENSE_TOTAL];   // 33.6 MB scratch (static, allowed)

// entry offsets of each dense level inside g_dense
#define DOFF2 0
#define DOFF3 15625
#define DOFF4 48393
#define DOFF5 112393
#define DOFF6 245044
#define DOFF7 507188
#define DOFF8 1038629

struct Corners { float2 g[8]; };

__device__ __forceinline__ void trilerp(
    const Corners& c, float tx, float ty, float tz, float& r0, float& r1)
{
    const float ux = 1.0f - tx, uy = 1.0f - ty, uz = 1.0f - tz;
    const float wy0z0 = uy * uz, wy1z0 = ty * uz;
    const float wy0z1 = uy * tz, wy1z1 = ty * tz;
    const float w000 = ux * wy0z0, w100 = tx * wy0z0;
    const float w010 = ux * wy1z0, w110 = tx * wy1z0;
    const float w001 = ux * wy0z1, w101 = tx * wy0z1;
    const float w011 = ux * wy1z1, w111 = tx * wy1z1;

    float a = w000 * c.g[0].x;
    float b = w000 * c.g[0].y;
    a = fmaf(w100, c.g[1].x, a);  b = fmaf(w100, c.g[1].y, b);
    a = fmaf(w010, c.g[2].x, a);  b = fmaf(w010, c.g[2].y, b);
    a = fmaf(w110, c.g[3].x, a);  b = fmaf(w110, c.g[3].y, b);
    a = fmaf(w001, c.g[4].x, a);  b = fmaf(w001, c.g[4].y, b);
    a = fmaf(w101, c.g[5].x, a);  b = fmaf(w101, c.g[5].y, b);
    a = fmaf(w011, c.g[6].x, a);  b = fmaf(w011, c.g[6].y, b);
    a = fmaf(w111, c.g[7].x, a);  b = fmaf(w111, c.g[7].y, b);
    r0 = a; r1 = b;
}

__device__ __forceinline__ void corner_setup(
    int N, float x, float y, float z,
    int& ix, int& iy, int& iz, int& ix1, int& iy1, int& iz1,
    float& tx, float& ty, float& tz)
{
    const float fN = (float)N;
    float sx = x * fN, sy = y * fN, sz = z * fN;
    float fx = floorf(sx), fy = floorf(sy), fz = floorf(sz);
    tx = sx - fx; ty = sy - fy; tz = sz - fz;
    ix = (int)fx; iy = (int)fy; iz = (int)fz;
    if (ix >= N) ix -= N;
    if (iy >= N) iy -= N;
    if (iz >= N) iz -= N;
    ix1 = ix + 1; if (ix1 >= N) ix1 -= N;
    iy1 = iy + 1; if (iy1 >= N) iy1 -= N;
    iz1 = iz + 1; if (iz1 >= N) iz1 -= N;
}

// hashed LDG level with x-parity LDG.128 merging (levels 9..15)
__device__ __forceinline__ void level_ldg(
    const float2* __restrict__ tbl, int N,
    float x, float y, float z, float& r0, float& r1)
{
    int ix, iy, iz, ix1, iy1, iz1;
    float tx, ty, tz;
    corner_setup(N, x, y, z, ix, iy, iz, ix1, iy1, iz1, tx, ty, tz);

    const uint32_t hy0 = (uint32_t)iy  * PY, hy1 = (uint32_t)iy1 * PY;
    const uint32_t hz0 = (uint32_t)iz  * PZ, hz1 = (uint32_t)iz1 * PZ;
    const uint32_t ux0 = (uint32_t)ix,  ux1 = (uint32_t)ix1;
    uint32_t s[4];
    s[0] = hy0 ^ hz0; s[1] = hy1 ^ hz0; s[2] = hy0 ^ hz1; s[3] = hy1 ^ hz1;

    Corners c;
    const bool pair = ((ix & 1) == 0) && (ix1 == ix + 1);
    if (pair) {
        const float4* __restrict__ tbl4 = (const float4*)tbl;
#pragma unroll
        for (int k = 0; k < 4; ++k) {
            uint32_t h0 = (ux0 ^ s[k]) & HMASK;          // h1 = h0 ^ 1
            float4 q = __ldg(tbl4 + (h0 >> 1));
            if (h0 & 1) { c.g[2*k] = make_float2(q.z, q.w); c.g[2*k+1] = make_float2(q.x, q.y); }
            else        { c.g[2*k] = make_float2(q.x, q.y); c.g[2*k+1] = make_float2(q.z, q.w); }
        }
    } else {
#pragma unroll
        for (int k = 0; k < 4; ++k) {
            uint32_t h0 = (ux0 ^ s[k]) & HMASK;
            uint32_t h1 = (ux1 ^ s[k]) & HMASK;
            c.g[2*k]   = __ldg(tbl + h0);
            c.g[2*k+1] = __ldg(tbl + h1);
        }
    }
    trilerp(c, tx, ty, tz, r0, r1);
}

// dense gmem level: x-pair + x-wrap baked into float4 entries (levels 2..8)
__device__ __forceinline__ void level_dense(
    const float4* __restrict__ t4, int N,
    float x, float y, float z, float& r0, float& r1)
{
    int ix, iy, iz, ix1, iy1, iz1;
    float tx, ty, tz;
    corner_setup(N, x, y, z, ix, iy, iz, ix1, iy1, iz1, tx, ty, tz);

    const int NN = N * N;
    const float4 q00 = __ldg(t4 + iz  * NN + iy  * N + ix);
    const float4 q10 = __ldg(t4 + iz  * NN + iy1 * N + ix);
    const float4 q01 = __ldg(t4 + iz1 * NN + iy  * N + ix);
    const float4 q11 = __ldg(t4 + iz1 * NN + iy1 * N + ix);

    Corners c;
    c.g[0] = make_float2(q00.x, q00.y); c.g[1] = make_float2(q00.z, q00.w);
    c.g[2] = make_float2(q10.x, q10.y); c.g[3] = make_float2(q10.z, q10.w);
    c.g[4] = make_float2(q01.x, q01.y); c.g[5] = make_float2(q01.z, q01.w);
    c.g[6] = make_float2(q11.x, q11.y); c.g[7] = make_float2(q11.z, q11.w);
    trilerp(c, tx, ty, tz, r0, r1);
}

// dense smem level (levels 0,1)
__device__ __forceinline__ void level_smem(
    const float2* __restrict__ stbl, int N,
    float x, float y, float z, float& r0, float& r1)
{
    int ix, iy, iz, ix1, iy1, iz1;
    float tx, ty, tz;
    corner_setup(N, x, y, z, ix, iy, iz, ix1, iy1, iz1, tx, ty, tz);

    const int y0 = iy * N,  y1 = iy1 * N;
    const int z0 = iz * N * N, z1 = iz1 * N * N;

    Corners c;
    c.g[0] = stbl[z0 + y0 + ix];  c.g[1] = stbl[z0 + y0 + ix1];
    c.g[2] = stbl[z0 + y1 + ix];  c.g[3] = stbl[z0 + y1 + ix1];
    c.g[4] = stbl[z1 + y0 + ix];  c.g[5] = stbl[z1 + y0 + ix1];
    c.g[6] = stbl[z1 + y1 + ix];  c.g[7] = stbl[z1 + y1 + ix1];
    trilerp(c, tx, ty, tz, r0, r1);
}

// ---- pre-kernel: materialize dense x-paired tables for levels 2..8 ----
__global__ void __launch_bounds__(256) build_dense_kernel(
    const float2* __restrict__ tables)
{
    const int i = blockIdx.x * blockDim.x + threadIdx.x;
    if (i >= DENSE_TOTAL) return;

    const int OFFS[7] = {DOFF2, DOFF3, DOFF4, DOFF5, DOFF6, DOFF7, DOFF8};
    const int DN[7]   = {25, 32, 40, 51, 64, 81, 102};

    int l = 0;
#pragma unroll
    for (int k = 1; k < 7; ++k) if (i >= OFFS[k]) l = k;

    const int local = i - OFFS[l];
    const int N = DN[l];
    const int ix = local % N;
    const int r  = local / N;
    const int iy = r % N;
    const int iz = r / N;
    const int ix1 = (ix + 1 == N) ? 0 : ix + 1;

    const float2* __restrict__ tbl = tables + (size_t)(l + 2) * T_SIZE;
    const uint32_t s = ((uint32_t)iy * PY) ^ ((uint32_t)iz * PZ);
    const float2 a = __ldg(tbl + (((uint32_t)ix  ^ s) & HMASK));
    const float2 b = __ldg(tbl + (((uint32_t)ix1 ^ s) & HMASK));
    g_dense[i] = make_float4(a.x, a.y, b.x, b.y);
}

__global__ void __launch_bounds__(1024, 1) hashgrid3d_kernel(
    const float* __restrict__ xyt,
    const float2* __restrict__ tables,
    float4* __restrict__ out,
    int n)
{
    extern __shared__ float2 smem[];
    float2* s0 = smem;               // level 0: dense 16^3
    float2* s1 = smem + S0_ENTRIES;  // level 1: dense 20^3

    // ---- build smem tables for levels 0,1 ----
    {
        const float2* __restrict__ t0 = tables;
        for (int i = threadIdx.x; i < S0_ENTRIES; i += 1024) {
            uint32_t ix =  i        & (N0 - 1);
            uint32_t iy = (i >> 4)  & (N0 - 1);
            uint32_t iz =  i >> 8;
            uint32_t h = (ix ^ (iy * PY) ^ (iz * PZ)) & HMASK;
            s0[i] = __ldg(t0 + h);
        }
        const float2* __restrict__ t1 = tables + T_SIZE;
        for (int i = threadIdx.x; i < S1_ENTRIES; i += 1024) {
            uint32_t ix = i % N1;
            uint32_t r  = i / N1;
            uint32_t iy = r % N1;
            uint32_t iz = r / N1;
            uint32_t h = (ix ^ (iy * PY) ^ (iz * PZ)) & HMASK;
            s1[i] = __ldg(t1 + h);
        }
    }
    __syncthreads();

    const int DN[7]   = {25, 32, 40, 51, 64, 81, 102};            // levels 2..8
    const int DOFF[7] = {DOFF2, DOFF3, DOFF4, DOFF5, DOFF6, DOFF7, DOFF8};
    const int HN[7]   = {128, 161, 203, 256, 323, 406, 512};      // levels 9..15

    const int stride = gridDim.x * blockDim.x;
    for (int p = blockIdx.x * blockDim.x + threadIdx.x; p < n; p += stride) {
        const float x = xyt[3 * p + 0];
        const float y = xyt[3 * p + 1];
        const float z = xyt[3 * p + 2];

        float4* o = out + (size_t)p * 8;
        float4 r;

        // levels 0,1 from smem
        level_smem(s0, N0, x, y, z, r.x, r.y);
        level_smem(s1, N1, x, y, z, r.z, r.w);
        o[0] = r;

        // levels 2..8 dense, 9 hashed -> outputs o[1..4]
        level_dense(g_dense + DOFF[0], DN[0], x, y, z, r.x, r.y);
        level_dense(g_dense + DOFF[1], DN[1], x, y, z, r.z, r.w);
        o[1] = r;
        level_dense(g_dense + DOFF[2], DN[2], x, y, z, r.x, r.y);
        level_dense(g_dense + DOFF[3], DN[3], x, y, z, r.z, r.w);
        o[2] = r;
        level_dense(g_dense + DOFF[4], DN[4], x, y, z, r.x, r.y);
        level_dense(g_dense + DOFF[5], DN[5], x, y, z, r.z, r.w);
        o[3] = r;
        level_dense(g_dense + DOFF[6], DN[6], x, y, z, r.x, r.y);
        level_ldg(tables + (size_t)9 * T_SIZE, HN[0], x, y, z, r.z, r.w);
        o[4] = r;

        // levels 10..15 hashed -> o[5..7]
#pragma unroll
        for (int g = 0; g < 3; ++g) {
            const int l0 = 1 + 2 * g, l1 = 2 + 2 * g;  // indices into HN
            level_ldg(tables + (size_t)(l0 + 9) * T_SIZE, HN[l0], x, y, z, r.x, r.y);
            level_ldg(tables + (size_t)(l1 + 9) * T_SIZE, HN[l1], x, y, z, r.z, r.w);
            o[5 + g] = r;
        }
    }
}

extern "C" void kernel_launch(void* const* d_in, const int* in_sizes, int n_in,
                              void* d_out, int out_size)
{
    const float*  xyt    = (const float*)d_in[0];
    const float2* tables = (const float2*)d_in[1];
    float4*       out    = (float4*)d_out;

    const int n = in_sizes[0] / 3;  // 1048576 points

    static bool attr_set = false;
    if (!attr_set) {
        cudaFuncSetAttribute(hashgrid3d_kernel,
                             cudaFuncAttributeMaxDynamicSharedMemorySize,
                             SMEM_BYTES);
        attr_set = true;
    }

    build_dense_kernel<<<(DENSE_TOTAL + 255) / 256, 256>>>(tables);
    hashgrid3d_kernel<<<148, 1024, SMEM_BYTES>>>(xyt, tables, out, n);
}

// round 5
// speedup vs baseline: 1.3891x; 1.1285x over previous
#include <cuda_runtime.h>
#include <cstdint>

// HashGrid3D: 16-level Instant-NGP style hash grid encode.
// xyt: (1048576, 3) fp32 in [0,1); tables: (16, 524288, 2) fp32.
// out: (1048576, 32) fp32.
//
// hash(c) = (cx*1 ^ cy*2654435761 ^ cz*805459861) & (T-1), T = 2^19.
//
// R5: kernel is L1tex-wavefront-count bound (model matches dur to 2%).
// Random uniform points -> zero line sharing. Fix the DATA ORDER:
// counting-sort points into 32^3 spatial buckets (~32 pts/bucket) so each
// warp covers a ~(1/32)^3 cube. Dense/smem levels (N<=102) then share
// cache lines heavily within a warp (saves ~600 wf/warp of 2560).
// Sort pipeline (zero/hist/scan/scatter) is ~1.5% overhead.
// Levels: 0-1 smem dense, 2-8 gmem dense x-paired float4, 9-15 hashed
// with x-parity LDG.128 pairing. Output written to out[orig_idx] ->
// deterministic regardless of atomic scatter order.

#define T_SIZE 524288u
#define HMASK  (T_SIZE - 1u)
#define PY     2654435761u
#define PZ     805459861u

#define NPTS 1048576

#define N0 16
#define N1 20
#define S0_ENTRIES (N0 * N0 * N0)          // 4096
#define S1_ENTRIES (N1 * N1 * N1)          // 8000
#define SMEM_BYTES ((S0_ENTRIES + S1_ENTRIES) * 8)  // 96768

// dense levels 2..8: N = 25,32,40,51,64,81,102
#define DENSE_TOTAL 2099837
__device__ float4 g_dense[DENSE_TOTAL];   // 33.6 MB scratch

#define DOFF2 0
#define DOFF3 15625
#define DOFF4 48393
#define DOFF5 112393
#define DOFF6 245044
#define DOFF7 507188
#define DOFF8 1038629

// ---- spatial binning scratch ----
#define NBDIM 32
#define NBUCKETS (NBDIM * NBDIM * NBDIM)   // 32768
__device__ uint32_t g_count[NBUCKETS];
__device__ float4   g_perm[NPTS];          // (x,y,z, bit-cast orig idx)

struct Corners { float2 g[8]; };

__device__ __forceinline__ void trilerp(
    const Corners& c, float tx, float ty, float tz, float& r0, float& r1)
{
    const float ux = 1.0f - tx, uy = 1.0f - ty, uz = 1.0f - tz;
    const float wy0z0 = uy * uz, wy1z0 = ty * uz;
    const float wy0z1 = uy * tz, wy1z1 = ty * tz;
    const float w000 = ux * wy0z0, w100 = tx * wy0z0;
    const float w010 = ux * wy1z0, w110 = tx * wy1z0;
    const float w001 = ux * wy0z1, w101 = tx * wy0z1;
    const float w011 = ux * wy1z1, w111 = tx * wy1z1;

    float a = w000 * c.g[0].x;
    float b = w000 * c.g[0].y;
    a = fmaf(w100, c.g[1].x, a);  b = fmaf(w100, c.g[1].y, b);
    a = fmaf(w010, c.g[2].x, a);  b = fmaf(w010, c.g[2].y, b);
    a = fmaf(w110, c.g[3].x, a);  b = fmaf(w110, c.g[3].y, b);
    a = fmaf(w001, c.g[4].x, a);  b = fmaf(w001, c.g[4].y, b);
    a = fmaf(w101, c.g[5].x, a);  b = fmaf(w101, c.g[5].y, b);
    a = fmaf(w011, c.g[6].x, a);  b = fmaf(w011, c.g[6].y, b);
    a = fmaf(w111, c.g[7].x, a);  b = fmaf(w111, c.g[7].y, b);
    r0 = a; r1 = b;
}

__device__ __forceinline__ void corner_setup(
    int N, float x, float y, float z,
    int& ix, int& iy, int& iz, int& ix1, int& iy1, int& iz1,
    float& tx, float& ty, float& tz)
{
    const float fN = (float)N;
    float sx = x * fN, sy = y * fN, sz = z * fN;
    float fx = floorf(sx), fy = floorf(sy), fz = floorf(sz);
    tx = sx - fx; ty = sy - fy; tz = sz - fz;
    ix = (int)fx; iy = (int)fy; iz = (int)fz;
    if (ix >= N) ix -= N;
    if (iy >= N) iy -= N;
    if (iz >= N) iz -= N;
    ix1 = ix + 1; if (ix1 >= N) ix1 -= N;
    iy1 = iy + 1; if (iy1 >= N) iy1 -= N;
    iz1 = iz + 1; if (iz1 >= N) iz1 -= N;
}

// hashed LDG level with x-parity LDG.128 merging (levels 9..15)
__device__ __forceinline__ void level_ldg(
    const float2* __restrict__ tbl, int N,
    float x, float y, float z, float& r0, float& r1)
{
    int ix, iy, iz, ix1, iy1, iz1;
    float tx, ty, tz;
    corner_setup(N, x, y, z, ix, iy, iz, ix1, iy1, iz1, tx, ty, tz);

    const uint32_t hy0 = (uint32_t)iy  * PY, hy1 = (uint32_t)iy1 * PY;
    const uint32_t hz0 = (uint32_t)iz  * PZ, hz1 = (uint32_t)iz1 * PZ;
    const uint32_t ux0 = (uint32_t)ix,  ux1 = (uint32_t)ix1;
    uint32_t s[4];
    s[0] = hy0 ^ hz0; s[1] = hy1 ^ hz0; s[2] = hy0 ^ hz1; s[3] = hy1 ^ hz1;

    Corners c;
    const bool pair = ((ix & 1) == 0) && (ix1 == ix + 1);
    if (pair) {
        const float4* __restrict__ tbl4 = (const float4*)tbl;
#pragma unroll
        for (int k = 0; k < 4; ++k) {
            uint32_t h0 = (ux0 ^ s[k]) & HMASK;          // h1 = h0 ^ 1
            float4 q = __ldg(tbl4 + (h0 >> 1));
            if (h0 & 1) { c.g[2*k] = make_float2(q.z, q.w); c.g[2*k+1] = make_float2(q.x, q.y); }
            else        { c.g[2*k] = make_float2(q.x, q.y); c.g[2*k+1] = make_float2(q.z, q.w); }
        }
    } else {
#pragma unroll
        for (int k = 0; k < 4; ++k) {
            uint32_t h0 = (ux0 ^ s[k]) & HMASK;
            uint32_t h1 = (ux1 ^ s[k]) & HMASK;
            c.g[2*k]   = __ldg(tbl + h0);
            c.g[2*k+1] = __ldg(tbl + h1);
        }
    }
    trilerp(c, tx, ty, tz, r0, r1);
}

// dense gmem level: x-pair + x-wrap baked into float4 entries (levels 2..8)
__device__ __forceinline__ void level_dense(
    const float4* __restrict__ t4, int N,
    float x, float y, float z, float& r0, float& r1)
{
    int ix, iy, iz, ix1, iy1, iz1;
    float tx, ty, tz;
    corner_setup(N, x, y, z, ix, iy, iz, ix1, iy1, iz1, tx, ty, tz);

    const int NN = N * N;
    const float4 q00 = __ldg(t4 + iz  * NN + iy  * N + ix);
    const float4 q10 = __ldg(t4 + iz  * NN + iy1 * N + ix);
    const float4 q01 = __ldg(t4 + iz1 * NN + iy  * N + ix);
    const float4 q11 = __ldg(t4 + iz1 * NN + iy1 * N + ix);

    Corners c;
    c.g[0] = make_float2(q00.x, q00.y); c.g[1] = make_float2(q00.z, q00.w);
    c.g[2] = make_float2(q10.x, q10.y); c.g[3] = make_float2(q10.z, q10.w);
    c.g[4] = make_float2(q01.x, q01.y); c.g[5] = make_float2(q01.z, q01.w);
    c.g[6] = make_float2(q11.x, q11.y); c.g[7] = make_float2(q11.z, q11.w);
    trilerp(c, tx, ty, tz, r0, r1);
}

// dense smem level (levels 0,1)
__device__ __forceinline__ void level_smem(
    const float2* __restrict__ stbl, int N,
    float x, float y, float z, float& r0, float& r1)
{
    int ix, iy, iz, ix1, iy1, iz1;
    float tx, ty, tz;
    corner_setup(N, x, y, z, ix, iy, iz, ix1, iy1, iz1, tx, ty, tz);

    const int y0 = iy * N,  y1 = iy1 * N;
    const int z0 = iz * N * N, z1 = iz1 * N * N;

    Corners c;
    c.g[0] = stbl[z0 + y0 + ix];  c.g[1] = stbl[z0 + y0 + ix1];
    c.g[2] = stbl[z0 + y1 + ix];  c.g[3] = stbl[z0 + y1 + ix1];
    c.g[4] = stbl[z1 + y0 + ix];  c.g[5] = stbl[z1 + y0 + ix1];
    c.g[6] = stbl[z1 + y1 + ix];  c.g[7] = stbl[z1 + y1 + ix1];
    trilerp(c, tx, ty, tz, r0, r1);
}

// ---- binning pipeline ----

__device__ __forceinline__ int bucket_of(float x, float y, float z)
{
    int bx = (int)(x * (float)NBDIM); if (bx > NBDIM - 1) bx = NBDIM - 1;
    int by = (int)(y * (float)NBDIM); if (by > NBDIM - 1) by = NBDIM - 1;
    int bz = (int)(z * (float)NBDIM); if (bz > NBDIM - 1) bz = NBDIM - 1;
    return (bz * NBDIM + by) * NBDIM + bx;
}

__global__ void __launch_bounds__(256) zero_kernel()
{
    const int i = blockIdx.x * blockDim.x + threadIdx.x;
    if (i < NBUCKETS) g_count[i] = 0;
}

__global__ void __launch_bounds__(256) hist_kernel(const float* __restrict__ xyt, int n)
{
    const int p = blockIdx.x * blockDim.x + threadIdx.x;
    if (p >= n) return;
    const float x = xyt[3 * p + 0];
    const float y = xyt[3 * p + 1];
    const float z = xyt[3 * p + 2];
    atomicAdd(&g_count[bucket_of(x, y, z)], 1u);
}

// single-block exclusive scan of g_count (32768 = 1024 threads x 32)
__global__ void __launch_bounds__(1024) scan_kernel()
{
    __shared__ uint32_t tsum[1024];
    const int t = threadIdx.x;
    const int base = t * 32;
    uint32_t vals[32];
    uint32_t s = 0;
#pragma unroll
    for (int j = 0; j < 32; ++j) { vals[j] = g_count[base + j]; s += vals[j]; }
    tsum[t] = s;
    __syncthreads();
    // Hillis-Steele inclusive scan over 1024 thread sums
    for (int off = 1; off < 1024; off <<= 1) {
        uint32_t v = (t >= off) ? tsum[t - off] : 0u;
        __syncthreads();
        tsum[t] += v;
        __syncthreads();
    }
    uint32_t run = (t == 0) ? 0u : tsum[t - 1];   // exclusive prefix
#pragma unroll
    for (int j = 0; j < 32; ++j) { uint32_t c = vals[j]; g_count[base + j] = run; run += c; }
}

__global__ void __launch_bounds__(256) scatter_kernel(const float* __restrict__ xyt, int n)
{
    const int p = blockIdx.x * blockDim.x + threadIdx.x;
    if (p >= n) return;
    const float x = xyt[3 * p + 0];
    const float y = xyt[3 * p + 1];
    const float z = xyt[3 * p + 2];
    const uint32_t slot = atomicAdd(&g_count[bucket_of(x, y, z)], 1u);
    g_perm[slot] = make_float4(x, y, z, __int_as_float(p));
}

// ---- pre-kernel: materialize dense x-paired tables for levels 2..8 ----
__global__ void __launch_bounds__(256) build_dense_kernel(
    const float2* __restrict__ tables)
{
    const int i = blockIdx.x * blockDim.x + threadIdx.x;
    if (i >= DENSE_TOTAL) return;

    const int OFFS[7] = {DOFF2, DOFF3, DOFF4, DOFF5, DOFF6, DOFF7, DOFF8};
    const int DN[7]   = {25, 32, 40, 51, 64, 81, 102};

    int l = 0;
#pragma unroll
    for (int k = 1; k < 7; ++k) if (i >= OFFS[k]) l = k;

    const int local = i - OFFS[l];
    const int N = DN[l];
    const int ix = local % N;
    const int r  = local / N;
    const int iy = r % N;
    const int iz = r / N;
    const int ix1 = (ix + 1 == N) ? 0 : ix + 1;

    const float2* __restrict__ tbl = tables + (size_t)(l + 2) * T_SIZE;
    const uint32_t s = ((uint32_t)iy * PY) ^ ((uint32_t)iz * PZ);
    const float2 a = __ldg(tbl + (((uint32_t)ix  ^ s) & HMASK));
    const float2 b = __ldg(tbl + (((uint32_t)ix1 ^ s) & HMASK));
    g_dense[i] = make_float4(a.x, a.y, b.x, b.y);
}

__global__ void __launch_bounds__(1024, 1) hashgrid3d_kernel(
    const float2* __restrict__ tables,
    float4* __restrict__ out,
    int n)
{
    extern __shared__ float2 smem[];
    float2* s0 = smem;               // level 0: dense 16^3
    float2* s1 = smem + S0_ENTRIES;  // level 1: dense 20^3

    // ---- build smem tables for levels 0,1 ----
    {
        const float2* __restrict__ t0 = tables;
        for (int i = threadIdx.x; i < S0_ENTRIES; i += 1024) {
            uint32_t ix =  i        & (N0 - 1);
            uint32_t iy = (i >> 4)  & (N0 - 1);
            uint32_t iz =  i >> 8;
            uint32_t h = (ix ^ (iy * PY) ^ (iz * PZ)) & HMASK;
            s0[i] = __ldg(t0 + h);
        }
        const float2* __restrict__ t1 = tables + T_SIZE;
        for (int i = threadIdx.x; i < S1_ENTRIES; i += 1024) {
            uint32_t ix = i % N1;
            uint32_t r  = i / N1;
            uint32_t iy = r % N1;
            uint32_t iz = r / N1;
            uint32_t h = (ix ^ (iy * PY) ^ (iz * PZ)) & HMASK;
            s1[i] = __ldg(t1 + h);
        }
    }
    __syncthreads();

    const int DN[7]   = {25, 32, 40, 51, 64, 81, 102};            // levels 2..8
    const int DOFF[7] = {DOFF2, DOFF3, DOFF4, DOFF5, DOFF6, DOFF7, DOFF8};
    const int HN[7]   = {128, 161, 203, 256, 323, 406, 512};      // levels 9..15

    const int stride = gridDim.x * blockDim.x;
    for (int i = blockIdx.x * blockDim.x + threadIdx.x; i < n; i += stride) {
        const float4 q = __ldg(g_perm + i);   // coalesced; spatially sorted
        const float x = q.x, y = q.y, z = q.z;
        const int p = __float_as_int(q.w);    // original point index

        float4* o = out + (size_t)p * 8;
        float4 r;

        // levels 0,1 from smem
        level_smem(s0, N0, x, y, z, r.x, r.y);
        level_smem(s1, N1, x, y, z, r.z, r.w);
        o[0] = r;

        // levels 2..8 dense, 9 hashed -> outputs o[1..4]
        level_dense(g_dense + DOFF[0], DN[0], x, y, z, r.x, r.y);
        level_dense(g_dense + DOFF[1], DN[1], x, y, z, r.z, r.w);
        o[1] = r;
        level_dense(g_dense + DOFF[2], DN[2], x, y, z, r.x, r.y);
        level_dense(g_dense + DOFF[3], DN[3], x, y, z, r.z, r.w);
        o[2] = r;
        level_dense(g_dense + DOFF[4], DN[4], x, y, z, r.x, r.y);
        level_dense(g_dense + DOFF[5], DN[5], x, y, z, r.z, r.w);
        o[3] = r;
        level_dense(g_dense + DOFF[6], DN[6], x, y, z, r.x, r.y);
        level_ldg(tables + (size_t)9 * T_SIZE, HN[0], x, y, z, r.z, r.w);
        o[4] = r;

        // levels 10..15 hashed -> o[5..7]
#pragma unroll
        for (int g = 0; g < 3; ++g) {
            const int l0 = 1 + 2 * g, l1 = 2 + 2 * g;  // indices into HN
            level_ldg(tables + (size_t)(l0 + 9) * T_SIZE, HN[l0], x, y, z, r.x, r.y);
            level_ldg(tables + (size_t)(l1 + 9) * T_SIZE, HN[l1], x, y, z, r.z, r.w);
            o[5 + g] = r;
        }
    }
}

extern "C" void kernel_launch(void* const* d_in, const int* in_sizes, int n_in,
                              void* d_out, int out_size)
{
    const float*  xyt    = (const float*)d_in[0];
    const float2* tables = (const float2*)d_in[1];
    float4*       out    = (float4*)d_out;

    const int n = in_sizes[0] / 3;  // 1048576 points

    static bool attr_set = false;
    if (!attr_set) {
        cudaFuncSetAttribute(hashgrid3d_kernel,
                             cudaFuncAttributeMaxDynamicSharedMemorySize,
                             SMEM_BYTES);
        attr_set = true;
    }

    // spatial counting-sort pipeline (deterministic final output: each
    // out[orig] depends only on that point's coordinates)
    zero_kernel<<<(NBUCKETS + 255) / 256, 256>>>();
    hist_kernel<<<(n + 255) / 256, 256>>>(xyt, n);
    scan_kernel<<<1, 1024>>>();
    scatter_kernel<<<(n + 255) / 256, 256>>>(xyt, n);

    build_dense_kernel<<<(DENSE_TOTAL + 255) / 256, 256>>>(tables);
    hashgrid3d_kernel<<<148, 1024, SMEM_BYTES>>>(tables, out, n);
}

// round 6
// speedup vs baseline: 1.4116x; 1.0162x over previous
#include <cuda_runtime.h>
#include <cstdint>

// HashGrid3D: 16-level Instant-NGP style hash grid encode.
// xyt: (1048576, 3) fp32 in [0,1); tables: (16, 524288, 2) fp32.
// out: (1048576, 32) fp32.
//
// hash(c) = (cx*1 ^ cy*2654435761 ^ cz*805459861) & (T-1), T = 2^19.
//
// R6: main kernel is at its structural wavefront floor (~2000 wf/warp);
// shave the auxiliary pipeline instead:
//  - scatter de-atomized: hist records per-point rank from its atomicAdd,
//    scan converts counts->bases in place, scatter is pure load+store
//  - build_dense: 2 entries/thread sharing a corner gather
//    (1 LDG.128 + 1 LDG.64 per 2 entries instead of 4 LDG.64)
// Main kernel unchanged: spatially sorted points, levels 0-1 smem dense,
// 2-8 gmem dense x-paired float4, 9-15 hashed with x-parity LDG.128.

#define T_SIZE 524288u
#define HMASK  (T_SIZE - 1u)
#define PY     2654435761u
#define PZ     805459861u

#define NPTS 1048576

#define N0 16
#define N1 20
#define S0_ENTRIES (N0 * N0 * N0)          // 4096
#define S1_ENTRIES (N1 * N1 * N1)          // 8000
#define SMEM_BYTES ((S0_ENTRIES + S1_ENTRIES) * 8)  // 96768

// dense levels 2..8: N = 25,32,40,51,64,81,102
#define DENSE_TOTAL 2099837
__device__ float4 g_dense[DENSE_TOTAL];   // 33.6 MB scratch

#define DOFF2 0
#define DOFF3 15625
#define DOFF4 48393
#define DOFF5 112393
#define DOFF6 245044
#define DOFF7 507188
#define DOFF8 1038629

// build: one thread per x-PAIR of entries. pairs per level = ceil(N/2)*N*N
// N:      25,    32,    40,    51,    64,    81,    102
// pairs: 8125, 16384, 32000, 33813, 131072/2... compute: ceil(N/2)*N^2
// 13*625=8125; 16*1024=16384; 20*1600=32000; 26*2601=67626; 32*4096=131072;
// 41*6561=269001; 51*10404=530604.  total pairs:
#define BPAIRS_TOTAL (8125 + 16384 + 32000 + 67626 + 131072 + 269001 + 530604) // 1054812
#define BP0 0
#define BP1 8125
#define BP2 24509
#define BP3 56509
#define BP4 124135
#define BP5 255207
#define BP6 524208

// ---- spatial binning scratch ----
#define NBDIM 32
#define NBUCKETS (NBDIM * NBDIM * NBDIM)   // 32768
__device__ uint32_t g_count[NBUCKETS];     // counts -> exclusive bases (scan)
__device__ uint32_t g_rank[NPTS];          // per-point rank within bucket
__device__ float4   g_perm[NPTS];          // (x,y,z, bit-cast orig idx)

struct Corners { float2 g[8]; };

__device__ __forceinline__ void trilerp(
    const Corners& c, float tx, float ty, float tz, float& r0, float& r1)
{
    const float ux = 1.0f - tx, uy = 1.0f - ty, uz = 1.0f - tz;
    const float wy0z0 = uy * uz, wy1z0 = ty * uz;
    const float wy0z1 = uy * tz, wy1z1 = ty * tz;
    const float w000 = ux * wy0z0, w100 = tx * wy0z0;
    const float w010 = ux * wy1z0, w110 = tx * wy1z0;
    const float w001 = ux * wy0z1, w101 = tx * wy0z1;
    const float w011 = ux * wy1z1, w111 = tx * wy1z1;

    float a = w000 * c.g[0].x;
    float b = w000 * c.g[0].y;
    a = fmaf(w100, c.g[1].x, a);  b = fmaf(w100, c.g[1].y, b);
    a = fmaf(w010, c.g[2].x, a);  b = fmaf(w010, c.g[2].y, b);
    a = fmaf(w110, c.g[3].x, a);  b = fmaf(w110, c.g[3].y, b);
    a = fmaf(w001, c.g[4].x, a);  b = fmaf(w001, c.g[4].y, b);
    a = fmaf(w101, c.g[5].x, a);  b = fmaf(w101, c.g[5].y, b);
    a = fmaf(w011, c.g[6].x, a);  b = fmaf(w011, c.g[6].y, b);
    a = fmaf(w111, c.g[7].x, a);  b = fmaf(w111, c.g[7].y, b);
    r0 = a; r1 = b;
}

__device__ __forceinline__ void corner_setup(
    int N, float x, float y, float z,
    int& ix, int& iy, int& iz, int& ix1, int& iy1, int& iz1,
    float& tx, float& ty, float& tz)
{
    const float fN = (float)N;
    float sx = x * fN, sy = y * fN, sz = z * fN;
    float fx = floorf(sx), fy = floorf(sy), fz = floorf(sz);
    tx = sx - fx; ty = sy - fy; tz = sz - fz;
    ix = (int)fx; iy = (int)fy; iz = (int)fz;
    if (ix >= N) ix -= N;
    if (iy >= N) iy -= N;
    if (iz >= N) iz -= N;
    ix1 = ix + 1; if (ix1 >= N) ix1 -= N;
    iy1 = iy + 1; if (iy1 >= N) iy1 -= N;
    iz1 = iz + 1; if (iz1 >= N) iz1 -= N;
}

// hashed LDG level with x-parity LDG.128 merging (levels 9..15)
__device__ __forceinline__ void level_ldg(
    const float2* __restrict__ tbl, int N,
    float x, float y, float z, float& r0, float& r1)
{
    int ix, iy, iz, ix1, iy1, iz1;
    float tx, ty, tz;
    corner_setup(N, x, y, z, ix, iy, iz, ix1, iy1, iz1, tx, ty, tz);

    const uint32_t hy0 = (uint32_t)iy  * PY, hy1 = (uint32_t)iy1 * PY;
    const uint32_t hz0 = (uint32_t)iz  * PZ, hz1 = (uint32_t)iz1 * PZ;
    const uint32_t ux0 = (uint32_t)ix,  ux1 = (uint32_t)ix1;
    uint32_t s[4];
    s[0] = hy0 ^ hz0; s[1] = hy1 ^ hz0; s[2] = hy0 ^ hz1; s[3] = hy1 ^ hz1;

    Corners c;
    const bool pair = ((ix & 1) == 0) && (ix1 == ix + 1);
    if (pair) {
        const float4* __restrict__ tbl4 = (const float4*)tbl;
#pragma unroll
        for (int k = 0; k < 4; ++k) {
            uint32_t h0 = (ux0 ^ s[k]) & HMASK;          // h1 = h0 ^ 1
            float4 q = __ldg(tbl4 + (h0 >> 1));
            if (h0 & 1) { c.g[2*k] = make_float2(q.z, q.w); c.g[2*k+1] = make_float2(q.x, q.y); }
            else        { c.g[2*k] = make_float2(q.x, q.y); c.g[2*k+1] = make_float2(q.z, q.w); }
        }
    } else {
#pragma unroll
        for (int k = 0; k < 4; ++k) {
            uint32_t h0 = (ux0 ^ s[k]) & HMASK;
            uint32_t h1 = (ux1 ^ s[k]) & HMASK;
            c.g[2*k]   = __ldg(tbl + h0);
            c.g[2*k+1] = __ldg(tbl + h1);
        }
    }
    trilerp(c, tx, ty, tz, r0, r1);
}

// dense gmem level: x-pair + x-wrap baked into float4 entries (levels 2..8)
__device__ __forceinline__ void level_dense(
    const float4* __restrict__ t4, int N,
    float x, float y, float z, float& r0, float& r1)
{
    int ix, iy, iz, ix1, iy1, iz1;
    float tx, ty, tz;
    corner_setup(N, x, y, z, ix, iy, iz, ix1, iy1, iz1, tx, ty, tz);

    const int NN = N * N;
    const float4 q00 = __ldg(t4 + iz  * NN + iy  * N + ix);
    const float4 q10 = __ldg(t4 + iz  * NN + iy1 * N + ix);
    const float4 q01 = __ldg(t4 + iz1 * NN + iy  * N + ix);
    const float4 q11 = __ldg(t4 + iz1 * NN + iy1 * N + ix);

    Corners c;
    c.g[0] = make_float2(q00.x, q00.y); c.g[1] = make_float2(q00.z, q00.w);
    c.g[2] = make_float2(q10.x, q10.y); c.g[3] = make_float2(q10.z, q10.w);
    c.g[4] = make_float2(q01.x, q01.y); c.g[5] = make_float2(q01.z, q01.w);
    c.g[6] = make_float2(q11.x, q11.y); c.g[7] = make_float2(q11.z, q11.w);
    trilerp(c, tx, ty, tz, r0, r1);
}

// dense smem level (levels 0,1)
__device__ __forceinline__ void level_smem(
    const float2* __restrict__ stbl, int N,
    float x, float y, float z, float& r0, float& r1)
{
    int ix, iy, iz, ix1, iy1, iz1;
    float tx, ty, tz;
    corner_setup(N, x, y, z, ix, iy, iz, ix1, iy1, iz1, tx, ty, tz);

    const int y0 = iy * N,  y1 = iy1 * N;
    const int z0 = iz * N * N, z1 = iz1 * N * N;

    Corners c;
    c.g[0] = stbl[z0 + y0 + ix];  c.g[1] = stbl[z0 + y0 + ix1];
    c.g[2] = stbl[z0 + y1 + ix];  c.g[3] = stbl[z0 + y1 + ix1];
    c.g[4] = stbl[z1 + y0 + ix];  c.g[5] = stbl[z1 + y0 + ix1];
    c.g[6] = stbl[z1 + y1 + ix];  c.g[7] = stbl[z1 + y1 + ix1];
    trilerp(c, tx, ty, tz, r0, r1);
}

// ---- binning pipeline ----

__device__ __forceinline__ int bucket_of(float x, float y, float z)
{
    int bx = (int)(x * (float)NBDIM); if (bx > NBDIM - 1) bx = NBDIM - 1;
    int by = (int)(y * (float)NBDIM); if (by > NBDIM - 1) by = NBDIM - 1;
    int bz = (int)(z * (float)NBDIM); if (bz > NBDIM - 1) bz = NBDIM - 1;
    return (bz * NBDIM + by) * NBDIM + bx;
}

__global__ void __launch_bounds__(256) zero_kernel()
{
    const int i = blockIdx.x * blockDim.x + threadIdx.x;
    if (i < NBUCKETS) g_count[i] = 0;
}

// histogram + record per-point rank (the atomic lives here, off scatter's path)
__global__ void __launch_bounds__(256) hist_kernel(const float* __restrict__ xyt, int n)
{
    const int p = blockIdx.x * blockDim.x + threadIdx.x;
    if (p >= n) return;
    const float x = xyt[3 * p + 0];
    const float y = xyt[3 * p + 1];
    const float z = xyt[3 * p + 2];
    g_rank[p] = atomicAdd(&g_count[bucket_of(x, y, z)], 1u);
}

// single-block exclusive scan of g_count (32768 = 1024 threads x 32), in place
__global__ void __launch_bounds__(1024) scan_kernel()
{
    __shared__ uint32_t tsum[1024];
    const int t = threadIdx.x;
    const int base = t * 32;
    uint32_t vals[32];
    uint32_t s = 0;
#pragma unroll
    for (int j = 0; j < 32; ++j) { vals[j] = g_count[base + j]; s += vals[j]; }
    tsum[t] = s;
    __syncthreads();
    for (int off = 1; off < 1024; off <<= 1) {
        uint32_t v = (t >= off) ? tsum[t - off] : 0u;
        __syncthreads();
        tsum[t] += v;
        __syncthreads();
    }
    uint32_t run = (t == 0) ? 0u : tsum[t - 1];   // exclusive prefix
#pragma unroll
    for (int j = 0; j < 32; ++j) { uint32_t c = vals[j]; g_count[base + j] = run; run += c; }
}

// atomic-free scatter: slot = base[bucket] + rank[p]
__global__ void __launch_bounds__(256) scatter_kernel(const float* __restrict__ xyt, int n)
{
    const int p = blockIdx.x * blockDim.x + threadIdx.x;
    if (p >= n) return;
    const float x = xyt[3 * p + 0];
    const float y = xyt[3 * p + 1];
    const float z = xyt[3 * p + 2];
    const uint32_t slot = g_count[bucket_of(x, y, z)] + g_rank[p];
    g_perm[slot] = make_float4(x, y, z, __int_as_float(p));
}

// ---- pre-kernel: materialize dense x-paired tables for levels 2..8 ----
// one thread per x-PAIR of entries (ix=2j, 2j+1): needs g(2j),g(2j+1),g(2j+2)
// = 1 LDG.128 (even-x chunk) + 1 LDG.64.
__global__ void __launch_bounds__(256) build_dense_kernel(
    const float2* __restrict__ tables)
{
    const int i = blockIdx.x * blockDim.x + threadIdx.x;
    if (i >= BPAIRS_TOTAL) return;

    const int POFF[7]  = {BP0, BP1, BP2, BP3, BP4, BP5, BP6};
    const int DOFF[7]  = {DOFF2, DOFF3, DOFF4, DOFF5, DOFF6, DOFF7, DOFF8};
    const int DN[7]    = {25, 32, 40, 51, 64, 81, 102};

    int l = 0;
#pragma unroll
    for (int k = 1; k < 7; ++k) if (i >= POFF[k]) l = k;

    const int N = DN[l];
    const int hw = (N + 1) >> 1;        // pairs per row
    const int local = i - POFF[l];
    const int pi = local % hw;
    const int r  = local / hw;
    const int iy = r % N;
    const int iz = r / N;
    const int ix = 2 * pi;

    const float2* __restrict__ tbl  = tables + (size_t)(l + 2) * T_SIZE;
    const float4* __restrict__ tbl4 = (const float4*)tbl;
    const uint32_t s = ((uint32_t)iy * PY) ^ ((uint32_t)iz * PZ);

    // chunk containing g(ix), g(ix^1)=g(ix+1) (ix even)
    const uint32_t h0 = ((uint32_t)ix ^ s) & HMASK;
    const float4 q = __ldg(tbl4 + (h0 >> 1));
    float2 ga, gb;   // g(ix), g(ix+1)
    if (h0 & 1) { ga = make_float2(q.z, q.w); gb = make_float2(q.x, q.y); }
    else        { ga = make_float2(q.x, q.y); gb = make_float2(q.z, q.w); }

    // g(ix+2) (wrapped) for the second entry
    const int x2 = (ix + 2 < N) ? ix + 2 : ix + 2 - N;
    const float2 gc = __ldg(tbl + (((uint32_t)x2 ^ s) & HMASK));

    float4* dst = g_dense + DOFF[l] + (size_t)(iz * N + iy) * N + ix;
    if (ix + 1 < N) {
        dst[0] = make_float4(ga.x, ga.y, gb.x, gb.y);   // entry ix:   (g(ix), g(ix+1))
        dst[1] = make_float4(gb.x, gb.y, gc.x, gc.y);   // entry ix+1: (g(ix+1), g(ix+2))
    } else {
        // odd N, last lone entry: (g(N-1), g(0)); g(0) = x2 path (x2==0 here... )
        // ix = N-1 even (N odd): pair chunk gave ga=g(N-1); need g(0):
        const float2 g0 = __ldg(tbl + (s & HMASK));     // x=0 -> h = s
        dst[0] = make_float4(ga.x, ga.y, g0.x, g0.y);
    }
}

__global__ void __launch_bounds__(1024, 1) hashgrid3d_kernel(
    const float2* __restrict__ tables,
    float4* __restrict__ out,
    int n)
{
    extern __shared__ float2 smem[];
    float2* s0 = smem;               // level 0: dense 16^3
    float2* s1 = smem + S0_ENTRIES;  // level 1: dense 20^3

    // ---- build smem tables for levels 0,1 ----
    {
        const float2* __restrict__ t0 = tables;
        for (int i = threadIdx.x; i < S0_ENTRIES; i += 1024) {
            uint32_t ix =  i        & (N0 - 1);
            uint32_t iy = (i >> 4)  & (N0 - 1);
            uint32_t iz =  i >> 8;
            uint32_t h = (ix ^ (iy * PY) ^ (iz * PZ)) & HMASK;
            s0[i] = __ldg(t0 + h);
        }
        const float2* __restrict__ t1 = tables + T_SIZE;
        for (int i = threadIdx.x; i < S1_ENTRIES; i += 1024) {
            uint32_t ix = i % N1;
            uint32_t r  = i / N1;
            uint32_t iy = r % N1;
            uint32_t iz = r / N1;
            uint32_t h = (ix ^ (iy * PY) ^ (iz * PZ)) & HMASK;
            s1[i] = __ldg(t1 + h);
        }
    }
    __syncthreads();

    const int DN[7]   = {25, 32, 40, 51, 64, 81, 102};            // levels 2..8
    const int DOFF[7] = {DOFF2, DOFF3, DOFF4, DOFF5, DOFF6, DOFF7, DOFF8};
    const int HN[7]   = {128, 161, 203, 256, 323, 406, 512};      // levels 9..15

    const int stride = gridDim.x * blockDim.x;
    for (int i = blockIdx.x * blockDim.x + threadIdx.x; i < n; i += stride) {
        const float4 q = __ldg(g_perm + i);   // coalesced; spatially sorted
        const float x = q.x, y = q.y, z = q.z;
        const int p = __float_as_int(q.w);    // original point index

        float4* o = out + (size_t)p * 8;
        float4 r;

        // levels 0,1 from smem
        level_smem(s0, N0, x, y, z, r.x, r.y);
        level_smem(s1, N1, x, y, z, r.z, r.w);
        o[0] = r;

        // levels 2..8 dense, 9 hashed -> outputs o[1..4]
        level_dense(g_dense + DOFF[0], DN[0], x, y, z, r.x, r.y);
        level_dense(g_dense + DOFF[1], DN[1], x, y, z, r.z, r.w);
        o[1] = r;
        level_dense(g_dense + DOFF[2], DN[2], x, y, z, r.x, r.y);
        level_dense(g_dense + DOFF[3], DN[3], x, y, z, r.z, r.w);
        o[2] = r;
        level_dense(g_dense + DOFF[4], DN[4], x, y, z, r.x, r.y);
        level_dense(g_dense + DOFF[5], DN[5], x, y, z, r.z, r.w);
        o[3] = r;
        level_dense(g_dense + DOFF[6], DN[6], x, y, z, r.x, r.y);
        level_ldg(tables + (size_t)9 * T_SIZE, HN[0], x, y, z, r.z, r.w);
        o[4] = r;

        // levels 10..15 hashed -> o[5..7]
#pragma unroll
        for (int g = 0; g < 3; ++g) {
            const int l0 = 1 + 2 * g, l1 = 2 + 2 * g;  // indices into HN
            level_ldg(tables + (size_t)(l0 + 9) * T_SIZE, HN[l0], x, y, z, r.x, r.y);
            level_ldg(tables + (size_t)(l1 + 9) * T_SIZE, HN[l1], x, y, z, r.z, r.w);
            o[5 + g] = r;
        }
    }
}

extern "C" void kernel_launch(void* const* d_in, const int* in_sizes, int n_in,
                              void* d_out, int out_size)
{
    const float*  xyt    = (const float*)d_in[0];
    const float2* tables = (const float2*)d_in[1];
    float4*       out    = (float4*)d_out;

    const int n = in_sizes[0] / 3;  // 1048576 points

    static bool attr_set = false;
    if (!attr_set) {
        cudaFuncSetAttribute(hashgrid3d_kernel,
                             cudaFuncAttributeMaxDynamicSharedMemorySize,
                             SMEM_BYTES);
        attr_set = true;
    }

    zero_kernel<<<(NBUCKETS + 255) / 256, 256>>>();
    hist_kernel<<<(n + 255) / 256, 256>>>(xyt, n);
    scan_kernel<<<1, 1024>>>();
    scatter_kernel<<<(n + 255) / 256, 256>>>(xyt, n);

    build_dense_kernel<<<(BPAIRS_TOTAL + 255) / 256, 256>>>(tables);
    hashgrid3d_kernel<<<148, 1024, SMEM_BYTES>>>(tables, out, n);
}